// round 2
// baseline (speedup 1.0000x reference)
#include <cuda_runtime.h>

#define B_  32
#define D_  256
#define H_  32
#define W_  32
#define HW_ 1024
#define N_  32768
#define K_  1024

#define TN 64
#define TK 64
#define TD 16

static const long long Q_OFF = (long long)B_ * D_ * H_ * W_;  // 8388608

__device__ int    g_idx[N_];
__device__ float  g_c2[K_];
__device__ float  g_x2[N_];
__device__ double g_acc;

// ---------------------------------------------------------------------------
// prep: codebook squared norms — sequential fp32, separate mul+add (no FMA),
// replicating XLA:CPU strict-FP scalar reduction. Also reset loss accumulator.
// ---------------------------------------------------------------------------
__global__ void prep_kernel(const float* __restrict__ cb) {
    int k = blockIdx.x * blockDim.x + threadIdx.x;
    if (k == 0 && blockIdx.x == 0) g_acc = 0.0;
    if (k < K_) {
        const float* r = cb + (size_t)k * D_;
        float s = 0.f;
        for (int d = 0; d < D_; ++d)
            s = __fadd_rn(s, __fmul_rn(r[d], r[d]));
        g_c2[k] = s;
    }
}

// x2[n] = sequential fp32 sum of x_d^2 over ascending d (no FMA).
__global__ void x2_kernel(const float* __restrict__ x) {
    int n = blockIdx.x * blockDim.x + threadIdx.x;
    if (n >= N_) return;
    const int b  = n / HW_;
    const int hw = n % HW_;
    const float* xb = x + (size_t)b * D_ * HW_ + hw;
    float s = 0.f;
    for (int d = 0; d < D_; ++d) {
        const float v = xb[(size_t)d * HW_];
        s = __fadd_rn(s, __fmul_rn(v, v));
    }
    g_x2[n] = s;
}

// ---------------------------------------------------------------------------
// fused distance GEMM + argmin with reference-exact fp32 rounding:
//   s      = ascending-d fp32 FMA chain (matches Eigen gebp sequential depth)
//   T      = fadd_rn(x2, -2*s)        (exact *2, one rounding)
//   d2     = fadd_rn(T, c2)           (one rounding)
//   argmin = first index among ties
// Block: 256 threads, 64 rows/block, codebook double-buffered 16x64 chunks.
// ---------------------------------------------------------------------------
__global__ __launch_bounds__(256, 2) void dist_kernel(
    const float* __restrict__ x, const float* __restrict__ cb)
{
    extern __shared__ float sm[];
    float* Xs = sm;                 // [D_][TN]
    float* Cs = sm + D_ * TN;       // [2][TD][TK]

    const int t   = threadIdx.x;
    const int n0  = blockIdx.x * TN;
    const int b   = n0 / HW_;
    const int hw0 = n0 % HW_;
    const float* xb = x + (size_t)b * D_ * HW_ + hw0;

#pragma unroll 8
    for (int i = 0; i < (D_ * TN) / 256; ++i) {
        int e = t + i * 256;
        int d = e >> 6, n = e & 63;
        Xs[d * TN + n] = xb[(size_t)d * HW_ + n];
    }
    __syncthreads();

    const int tx = t & 15, ty = t >> 4;
    const int kk_ld = t >> 2;
    const int dd_ld = (t & 3) << 2;

    float x2r[4];
#pragma unroll
    for (int i = 0; i < 4; ++i) x2r[i] = g_x2[n0 + (ty << 2) + i];

    float best[4];
    int   bidx[4];
#pragma unroll
    for (int i = 0; i < 4; ++i) { best[i] = 3.4e38f; bidx[i] = 0; }

    for (int k0 = 0; k0 < K_; k0 += TK) {
        float acc[4][4];
#pragma unroll
        for (int i = 0; i < 4; ++i)
#pragma unroll
            for (int j = 0; j < 4; ++j) acc[i][j] = 0.f;

        {
            const float4 v = *(const float4*)(cb + (size_t)(k0 + kk_ld) * D_ + dd_ld);
            float* c = Cs;
            c[(dd_ld + 0) * TK + kk_ld] = v.x;
            c[(dd_ld + 1) * TK + kk_ld] = v.y;
            c[(dd_ld + 2) * TK + kk_ld] = v.z;
            c[(dd_ld + 3) * TK + kk_ld] = v.w;
        }
        __syncthreads();

        int buf = 0;
#pragma unroll 1
        for (int dc = 0; dc < D_ / TD; ++dc) {
            if (dc + 1 < D_ / TD) {
                const float4 v = *(const float4*)(cb + (size_t)(k0 + kk_ld) * D_
                                                  + (dc + 1) * TD + dd_ld);
                float* c = Cs + (buf ^ 1) * TD * TK;
                c[(dd_ld + 0) * TK + kk_ld] = v.x;
                c[(dd_ld + 1) * TK + kk_ld] = v.y;
                c[(dd_ld + 2) * TK + kk_ld] = v.z;
                c[(dd_ld + 3) * TK + kk_ld] = v.w;
            }
            const float* cbuf = Cs + buf * TD * TK;
#pragma unroll
            for (int dd = 0; dd < TD; ++dd) {
                const float4 xf = *(const float4*)(Xs + (dc * TD + dd) * TN + (ty << 2));
                const float4 cf = *(const float4*)(cbuf + dd * TK + (tx << 2));
                acc[0][0] = fmaf(xf.x, cf.x, acc[0][0]);
                acc[0][1] = fmaf(xf.x, cf.y, acc[0][1]);
                acc[0][2] = fmaf(xf.x, cf.z, acc[0][2]);
                acc[0][3] = fmaf(xf.x, cf.w, acc[0][3]);
                acc[1][0] = fmaf(xf.y, cf.x, acc[1][0]);
                acc[1][1] = fmaf(xf.y, cf.y, acc[1][1]);
                acc[1][2] = fmaf(xf.y, cf.z, acc[1][2]);
                acc[1][3] = fmaf(xf.y, cf.w, acc[1][3]);
                acc[2][0] = fmaf(xf.z, cf.x, acc[2][0]);
                acc[2][1] = fmaf(xf.z, cf.y, acc[2][1]);
                acc[2][2] = fmaf(xf.z, cf.z, acc[2][2]);
                acc[2][3] = fmaf(xf.z, cf.w, acc[2][3]);
                acc[3][0] = fmaf(xf.w, cf.x, acc[3][0]);
                acc[3][1] = fmaf(xf.w, cf.y, acc[3][1]);
                acc[3][2] = fmaf(xf.w, cf.z, acc[3][2]);
                acc[3][3] = fmaf(xf.w, cf.w, acc[3][3]);
            }
            buf ^= 1;
            __syncthreads();
        }

        // fold with reference-exact rounding; ascending k + strict < keeps
        // first-min semantics of jnp.argmin
#pragma unroll
        for (int j = 0; j < 4; ++j) {
            const int   k   = k0 + (tx << 2) + j;
            const float c2k = g_c2[k];
#pragma unroll
            for (int i = 0; i < 4; ++i) {
                const float T  = __fadd_rn(x2r[i], -2.0f * acc[i][j]);
                const float dv = __fadd_rn(T, c2k);
                if (dv < best[i]) { best[i] = dv; bidx[i] = k; }
            }
        }
    }

#pragma unroll
    for (int i = 0; i < 4; ++i) {
        float v  = best[i];
        int   bi = bidx[i];
#pragma unroll
        for (int m = 8; m; m >>= 1) {
            const float v2 = __shfl_xor_sync(0xffffffffu, v, m);
            const int   b2 = __shfl_xor_sync(0xffffffffu, bi, m);
            if (v2 < v || (v2 == v && b2 < bi)) { v = v2; bi = b2; }
        }
        if (tx == 0) g_idx[n0 + (ty << 2) + i] = bi;
    }
}

// ---------------------------------------------------------------------------
// gather + straight-through output + loss partial sums + idx-as-float
// ---------------------------------------------------------------------------
__global__ __launch_bounds__(256) void quant_kernel(
    const float* __restrict__ x, const float* __restrict__ cb,
    float* __restrict__ out, long long out_size)
{
    __shared__ float red[256];
    const int t   = threadIdx.x;
    const int n0  = blockIdx.x * 64;
    const int b   = n0 / HW_;
    const int hw0 = n0 % HW_;
    const int tn  = t & 63;
    const int dz  = t >> 6;
    const int n   = n0 + tn;
    const int k   = g_idx[n];

    const float* xb = x   + (size_t)b * D_ * HW_ + hw0 + tn;
    float*       ob = out + (size_t)b * D_ * HW_ + hw0 + tn;
    const float* cr = cb  + (size_t)k * D_;

    float s = 0.f;
#pragma unroll 8
    for (int d = dz; d < D_; d += 4) {
        const float xv   = xb[(size_t)d * HW_];
        const float cv   = cr[d];
        const float diff = __fadd_rn(cv, -xv);        // q - x
        ob[(size_t)d * HW_] = __fadd_rn(xv, diff);    // x + (q - x)
        s = fmaf(diff, diff, s);
    }

    if (dz == 0 && out_size >= Q_OFF + 3 + N_)
        out[Q_OFF + 3 + n] = (float)k;

    red[t] = s;
    __syncthreads();
    for (int w = 128; w > 0; w >>= 1) {
        if (t < w) red[t] += red[t + w];
        __syncthreads();
    }
    if (t == 0) atomicAdd(&g_acc, (double)red[0]);
}

__global__ void finalize_kernel(float* __restrict__ out, long long out_size) {
    if (out_size >= Q_OFF + 3) {
        const double m = g_acc / (double)((long long)N_ * D_);
        const float  l = (float)m;
        out[Q_OFF + 0] = l;                     // q_loss
        out[Q_OFF + 1] = l;                     // e_loss
        out[Q_OFF + 2] = __fadd_rn(l, 0.25f * l);  // vq_loss
    }
}

// ---------------------------------------------------------------------------
extern "C" void kernel_launch(void* const* d_in, const int* in_sizes, int n_in,
                              void* d_out, int out_size)
{
    const float* x  = (const float*)d_in[0];
    const float* cb = (const float*)d_in[1];
    float*       out = (float*)d_out;
    const long long osz = (long long)out_size;

    const int smem = (D_ * TN + 2 * TD * TK) * (int)sizeof(float); // 73728 B
    cudaFuncSetAttribute(dist_kernel,
                         cudaFuncAttributeMaxDynamicSharedMemorySize, smem);

    prep_kernel<<<(K_ + 255) / 256, 256>>>(cb);
    x2_kernel<<<N_ / 256, 256>>>(x);
    dist_kernel<<<N_ / TN, 256, smem>>>(x, cb);
    quant_kernel<<<N_ / 64, 256>>>(x, cb, out, osz);
    finalize_kernel<<<1, 1>>>(out, osz);
}